// round 15
// baseline (speedup 1.0000x reference)
#include <cuda_runtime.h>
#include <cuda_fp16.h>
#include <cstdint>

#define Bb 4
#define Hh 16
#define Ll 8192
#define Dd 64
#define BH (Bb*Hh)
#define SCALE 0.10511205190671431f   // 8192^(-1/4)
#define NCHUNK 16
#define RPC (Ll/NCHUNK)              // 512 rows per chunk
#define NTILE (RPC/64)               // 8 tiles of 64 rows
#define PAD 72                       // f16 row stride (144B, conflict-free)
#define P2ROWS 256                   // rows per phase2 CTA
#define P2TILES (P2ROWS/64)          // 4

// __device__ scratch (allocation-free rule)
__device__ float g_scratch[(size_t)NCHUNK*BH*Dd*Dd];   // 16.7 MB fp32 partial KV
__device__ __half g_KVh[(size_t)BH*Dd*Dd];             // 0.5 MB fp16 KV
__device__ unsigned g_cnt[BH];                          // per-bh arrival counters (static zero)

// ---------------- helpers ----------------
__device__ __forceinline__ uint32_t s2u(const void* p) {
    uint32_t a;
    asm("{ .reg .u64 t; cvta.to.shared.u64 t, %1; cvt.u32.u64 %0, t; }" : "=r"(a) : "l"(p));
    return a;
}
__device__ __forceinline__ void ldsm4t(uint32_t addr, uint32_t* r) {
    asm volatile("ldmatrix.sync.aligned.m8n8.x4.trans.shared.b16 {%0,%1,%2,%3}, [%4];"
                 : "=r"(r[0]), "=r"(r[1]), "=r"(r[2]), "=r"(r[3]) : "r"(addr));
}
__device__ __forceinline__ void ldsm4(uint32_t addr, uint32_t* r) {
    asm volatile("ldmatrix.sync.aligned.m8n8.x4.shared.b16 {%0,%1,%2,%3}, [%4];"
                 : "=r"(r[0]), "=r"(r[1]), "=r"(r[2]), "=r"(r[3]) : "r"(addr));
}
// fp16 MMA, fp32 accumulate
__device__ __forceinline__ void mma16816(float* c, const uint32_t* a, uint32_t b0, uint32_t b1) {
    asm volatile("mma.sync.aligned.m16n8k16.row.col.f32.f16.f16.f32 "
                 "{%0,%1,%2,%3},{%4,%5,%6,%7},{%8,%9},{%0,%1,%2,%3};"
                 : "+f"(c[0]), "+f"(c[1]), "+f"(c[2]), "+f"(c[3])
                 : "r"(a[0]), "r"(a[1]), "r"(a[2]), "r"(a[3]), "r"(b0), "r"(b1));
}
__device__ __forceinline__ float elu_p1(float x) { float e = __expf(x); return x > 0.0f ? x + 1.0f : e; }
// pack (a -> lo half, b -> hi half) as fp16x2
__device__ __forceinline__ uint32_t pkh(float a, float b) {
    uint32_t r;
    asm("cvt.rn.f16x2.f32 %0, %1, %2;" : "=r"(r) : "f"(b), "f"(a));
    return r;
}

// ============================================================
// Phase 1: partial KV[d][e] = sum_l Kf[l][d]*Vm[l][e]  (fp16 single-pass)
// grid (NCHUNK, BH), 256 thr / 8 warps.
// Per tile: sync -> TRANSFORM(regs) -> LDG(t+1) -> sync -> MMA
// Epilogue: write partial; LAST CTA per bh reduces all 16 -> fp16 KV.
// ============================================================
__global__ void __launch_bounds__(256)
phase1_kernel(const float* __restrict__ Kp, const float* __restrict__ Vp,
              const float* __restrict__ maskp, const float* __restrict__ pip,
              const float* __restrict__ mup) {
    __shared__ __half khs[64*PAD], vhs[64*PAD];
    __shared__ float mus[64];
    __shared__ unsigned s_last;
    const int t = threadIdx.x, lane = t & 31, w = t >> 5;
    const int chunk = blockIdx.x, bhidx = blockIdx.y, b = bhidx / Hh, h = bhidx % Hh;

    const float p0 = fminf(fmaxf(pip[0], 0.f), 1.f);
    const float p1 = fminf(fmaxf(pip[1], 0.f), 1.f);
    const float ps = p0 + p1;
    if (t < 64) mus[t] = p0 * mup[h*64 + t] + p1 * mup[(Hh + h)*64 + t];

    const size_t base = ((size_t)bhidx*Ll + (size_t)chunk*RPC) * 64;
    const float* __restrict__ Kb = Kp + base;
    const float* __restrict__ Vb = Vp + base;
    const float* __restrict__ mb = maskp + (size_t)b*Ll + (size_t)chunk*RPC;

    const int md = (w & 3) * 16, ne = (w >> 2) * 32;
    const int gr = lane >> 3, r8 = lane & 7;
    const uint32_t aoff = ((uint32_t)((((gr & 2) ? 8 : 0) + r8) * PAD + md + ((gr & 1) ? 8 : 0))) * 2;
    const uint32_t boff = ((uint32_t)((((gr & 1) ? 8 : 0) + r8) * PAD + ne + ((gr & 2) ? 8 : 0))) * 2;
    const uint32_t skh = s2u(khs), svh = s2u(vhs);

    float acc[4][4];
#pragma unroll
    for (int i = 0; i < 4; i++)
#pragma unroll
        for (int j = 0; j < 4; j++) acc[i][j] = 0.f;

    float4 kreg[4], vreg[4];
    float  mreg[4];
    const int trow = t >> 4, tdq = (t & 15) * 4;

#define LOAD_TILE(tl) do { const int _l0 = (tl) * 64; \
    _Pragma("unroll") \
    for (int j = 0; j < 4; j++) { \
        const size_t off = (size_t)(_l0 + trow + 16*j)*64 + tdq; \
        kreg[j] = *(const float4*)(Kb + off); \
        vreg[j] = *(const float4*)(Vb + off); \
        mreg[j] = mb[_l0 + trow + 16*j]; \
    } } while (0)

#define TRANSFORM() do { \
    _Pragma("unroll") \
    for (int j = 0; j < 4; j++) { \
        const int row = trow + 16*j; \
        const float m = mreg[j], msc = m * SCALE; \
        float f0 = elu_p1(kreg[j].x*ps - mus[tdq+0]) * msc; \
        float f1 = elu_p1(kreg[j].y*ps - mus[tdq+1]) * msc; \
        float f2 = elu_p1(kreg[j].z*ps - mus[tdq+2]) * msc; \
        float f3 = elu_p1(kreg[j].w*ps - mus[tdq+3]) * msc; \
        uint2 kh = { pkh(f0, f1), pkh(f2, f3) }; \
        *(uint2*)&khs[row*PAD + tdq] = kh; \
        uint2 vh = { pkh(vreg[j].x * m, vreg[j].y * m), pkh(vreg[j].z * m, vreg[j].w * m) }; \
        *(uint2*)&vhs[row*PAD + tdq] = vh; \
    } } while (0)

    LOAD_TILE(0);

    for (int tile = 0; tile < NTILE; tile++) {
        __syncthreads();                  // prev MMA done; mus visible on tile 0
        TRANSFORM();
        if (tile + 1 < NTILE) LOAD_TILE(tile + 1);
        __syncthreads();

#pragma unroll
        for (int kl = 0; kl < 64; kl += 16) {
            const uint32_t kadd = (uint32_t)(kl * PAD * 2);
            uint32_t ah[4];
            ldsm4t(skh + kadd + aoff, ah);
            uint32_t bh0[4], bh1[4];
            ldsm4t(svh + kadd + boff,      bh0);
            ldsm4t(svh + kadd + boff + 32, bh1);
            mma16816(acc[0], ah, bh0[0], bh0[1]);
            mma16816(acc[1], ah, bh0[2], bh0[3]);
            mma16816(acc[2], ah, bh1[0], bh1[1]);
            mma16816(acc[3], ah, bh1[2], bh1[3]);
        }
    }
#undef LOAD_TILE
#undef TRANSFORM

    // write this CTA's partial KV
    float* outp = g_scratch + ((size_t)chunk*BH + bhidx) * 4096;
    const int rw = lane >> 2, cq = (lane & 3) * 2;
#pragma unroll
    for (int j = 0; j < 4; j++) {
        float2 lo = { acc[j][0], acc[j][1] };
        float2 hi = { acc[j][2], acc[j][3] };
        *(float2*)&outp[(md + rw) * 64 + ne + 8*j + cq]     = lo;
        *(float2*)&outp[(md + 8 + rw) * 64 + ne + 8*j + cq] = hi;
    }

    // last-CTA-per-bh reduces all 16 partials (fixed order -> deterministic)
    __threadfence();                               // partial visible before counter bump
    if (t == 0) s_last = (atomicAdd(&g_cnt[bhidx], 1u) == NCHUNK - 1) ? 1u : 0u;
    __syncthreads();
    if (s_last) {
        __threadfence();                           // other CTAs' partials visible
#pragma unroll
        for (int i = 0; i < 4; i++) {
            const int pos = t*4 + i*1024;
            float4 s = make_float4(0.f, 0.f, 0.f, 0.f);
#pragma unroll
            for (int c = 0; c < NCHUNK; c++) {
                const float4 v = *(const float4*)(g_scratch + ((size_t)c*BH + bhidx)*4096 + pos);
                s.x += v.x; s.y += v.y; s.z += v.z; s.w += v.w;
            }
            uint2 hv = { pkh(s.x, s.y), pkh(s.z, s.w) };
            *(uint2*)(g_KVh + (size_t)bhidx*4096 + pos) = hv;
        }
        __syncthreads();
        if (t == 0) g_cnt[bhidx] = 0;              // reset for next graph replay
    }
}

// ============================================================
// Phase 2: out[l][e] = sum_d Qf[l][d]*KV[d][e]  (fp16 single-pass)
// grid (Ll/P2ROWS, BH) = (32, 64), 256 thr / 8 warps.
// Each CTA: KV once, then 4 tiles of 64 Q rows:
//   sync -> TRANSQ(regs) -> LOADQ(t+1) -> sync -> MMA+STG
// ============================================================
__global__ void __launch_bounds__(256)
phase2_kernel(const float* __restrict__ Qp, float* __restrict__ outp) {
    __shared__ __half qhs[64*PAD], kvs[64*PAD];
    const int t = threadIdx.x, lane = t & 31, w = t >> 5;
    const int rb = blockIdx.x, bhidx = blockIdx.y;

    // KV tile once per CTA (L2-resident source)
    {
        const int row = t >> 2, cg = (t & 3) * 16;
        *(uint4*)&kvs[row*PAD + cg]     = *(const uint4*)(g_KVh + (size_t)bhidx*4096 + row*64 + cg);
        *(uint4*)&kvs[row*PAD + cg + 8] = *(const uint4*)(g_KVh + (size_t)bhidx*4096 + row*64 + cg + 8);
    }

    const float* __restrict__ Qb = Qp + ((size_t)bhidx*Ll + (size_t)rb*P2ROWS) * 64;
    float* __restrict__ Ob = outp + ((size_t)bhidx*Ll + (size_t)rb*P2ROWS) * 64;

    const int md = (w & 3) * 16, ne = (w >> 2) * 32;
    const int gr = lane >> 3, r8 = lane & 7;
    const uint32_t aoff = ((uint32_t)((md + ((gr & 1) ? 8 : 0) + r8) * PAD + ((gr & 2) ? 8 : 0))) * 2;
    const uint32_t boff = ((uint32_t)((((gr & 1) ? 8 : 0) + r8) * PAD + ne + ((gr & 2) ? 8 : 0))) * 2;
    const uint32_t sqh = s2u(qhs), svh = s2u(kvs);
    const int rw = lane >> 2, cq = (lane & 3) * 2;

    float4 qreg[4];
    const int trow = t >> 4, tdq = (t & 15) * 4;

#define LOADQ(tl) do { const int _l0 = (tl) * 64; \
    _Pragma("unroll") \
    for (int j = 0; j < 4; j++) { \
        qreg[j] = *(const float4*)(Qb + (size_t)(_l0 + trow + 16*j)*64 + tdq); \
    } } while (0)

#define TRANSQ() do { \
    _Pragma("unroll") \
    for (int j = 0; j < 4; j++) { \
        const int row = trow + 16*j; \
        float f0 = elu_p1(qreg[j].x) * SCALE, f1 = elu_p1(qreg[j].y) * SCALE; \
        float f2 = elu_p1(qreg[j].z) * SCALE, f3 = elu_p1(qreg[j].w) * SCALE; \
        uint2 qh = { pkh(f0, f1), pkh(f2, f3) }; \
        *(uint2*)&qhs[row*PAD + tdq] = qh; \
    } } while (0)

    LOADQ(0);

    for (int tile = 0; tile < P2TILES; tile++) {
        __syncthreads();                  // prev MMA done; KV visible on tile 0
        TRANSQ();
        if (tile + 1 < P2TILES) LOADQ(tile + 1);
        __syncthreads();

        float acc[4][4];
#pragma unroll
        for (int i = 0; i < 4; i++)
#pragma unroll
            for (int j = 0; j < 4; j++) acc[i][j] = 0.f;

#pragma unroll
        for (int kd = 0; kd < 64; kd += 16) {
            uint32_t ah[4];
            ldsm4(sqh + aoff + (uint32_t)(kd*2), ah);
#pragma unroll
            for (int p = 0; p < 2; p++) {
                const uint32_t badd = (uint32_t)(kd * PAD * 2 + p * 32);
                uint32_t vh[4];
                ldsm4t(svh + badd + boff, vh);
                mma16816(acc[2*p],   ah, vh[0], vh[1]);
                mma16816(acc[2*p+1], ah, vh[2], vh[3]);
            }
        }

        float* __restrict__ ob = Ob + (size_t)tile*64*64;
#pragma unroll
        for (int j = 0; j < 4; j++) {
            float2 lo = { acc[j][0], acc[j][1] };
            float2 hi = { acc[j][2], acc[j][3] };
            *(float2*)&ob[(md + rw) * 64 + ne + 8*j + cq]     = lo;
            *(float2*)&ob[(md + 8 + rw) * 64 + ne + 8*j + cq] = hi;
        }
    }
#undef LOADQ
#undef TRANSQ
}

// ============================================================
// Launch
// ============================================================
extern "C" void kernel_launch(void* const* d_in, const int* in_sizes, int n_in,
                              void* d_out, int out_size) {
    const float* Q    = (const float*)d_in[0];
    const float* K    = (const float*)d_in[1];
    const float* V    = (const float*)d_in[2];
    const float* mask = (const float*)d_in[3];
    const float* pi   = (const float*)d_in[4];
    const float* mu   = (const float*)d_in[5];
    float* out = (float*)d_out;

    dim3 g1(NCHUNK, BH);
    phase1_kernel<<<g1, 256>>>(K, V, mask, pi, mu);
    dim3 g3(Ll / P2ROWS, BH);
    phase2_kernel<<<g3, 256>>>(Q, out);
}